// round 7
// baseline (speedup 1.0000x reference)
#include <cuda_runtime.h>

// Problem constants (static per reference)
#define BSZ   128
#define NTOT  129
#define NPT   128          // N
#define GS    16
#define CH    384          // channels
#define CH4   96           // CH / 4
#define EPSW  0.05f
#define RMSEPS 1e-6f

__global__ __launch_bounds__(96, 8)
void K_Rectify_38216619000515_kernel(
    const float* __restrict__ f,        // (B, NTOT, CH)
    const float* __restrict__ distance, // (B, N, GS)
    const float* __restrict__ rf,       // (NTOT, CH)
    const float* __restrict__ knorm_w,  // (CH,)
    const int*   __restrict__ idx,      // (B, N, GS), int32, values in [0, B*N)
    float*       __restrict__ out)      // (B, NTOT, CH)
{
    const int bid = blockIdx.x;          // 0..4095, four points per block
    const int bn0 = bid << 2;
    const int tid = threadIdx.x;         // 0..95
    const int w   = tid >> 5;
    const int lane = tid & 31;

    __shared__ float2 sgw[4][GS];        // {row offset (int bits), weight}
    __shared__ float  red[4][3];

    if (tid < 4 * GS) {
        const int p  = tid >> 4;         // point 0..3
        const int g  = tid & 15;
        const int bn = bn0 + p;
        float d  = distance[bn * GS + g];
        float wt = 1.0f / (d + EPSW);
        int r    = idx[bn * GS + g] & (BSZ * NPT - 1);
        int off  = ((r >> 7) * NTOT + (r & 127) + 1) * CH4;   // float4 units
        sgw[p][g] = make_float2(__int_as_float(off), wt);
    }

    const int b  = bn0 >> 7;             // all 4 points share b (N % 4 == 0)
    const int n0 = bn0 & 127;            // multiple of 4; only p=0 can be n==0

    // cls token passthrough; 96 lanes == CH4 float4s
    if (n0 == 0) {
        ((float4*)out)[b * (NTOT * CH4) + tid] =
            __ldg((const float4*)f + b * (NTOT * CH4) + tid);
    }
    __syncthreads();

    float ws0 = 0.f, ws1 = 0.f, ws2 = 0.f, ws3 = 0.f;
#pragma unroll
    for (int g = 0; g < GS; ++g) {
        ws0 += sgw[0][g].y; ws1 += sgw[1][g].y;
        ws2 += sgw[2][g].y; ws3 += sgw[3][g].y;
    }
    const float iw0 = 1.0f / ws0, iw1 = 1.0f / ws1;
    const float iw2 = 1.0f / ws2, iw3 = 1.0f / ws3;

    const float4* f4 = (const float4*)f;
    const int xrow0 = (b * NTOT + 1 + n0) * CH4;   // rows 0..3 contiguous: +CH4 each

    float4 s0 = make_float4(0.f,0.f,0.f,0.f);
    float4 s1 = make_float4(0.f,0.f,0.f,0.f);
    float4 s2 = make_float4(0.f,0.f,0.f,0.f);
    float4 s3 = make_float4(0.f,0.f,0.f,0.f);
#pragma unroll
    for (int g = 0; g < GS; ++g) {
        const float2 g0 = sgw[0][g];
        const float2 g1 = sgw[1][g];
        const float2 g2 = sgw[2][g];
        const float2 g3 = sgw[3][g];
        const float4 v0 = __ldg(f4 + __float_as_int(g0.x) + tid);
        const float4 v1 = __ldg(f4 + __float_as_int(g1.x) + tid);
        const float4 v2 = __ldg(f4 + __float_as_int(g2.x) + tid);
        const float4 v3 = __ldg(f4 + __float_as_int(g3.x) + tid);
        s0.x = fmaf(g0.y, v0.x, s0.x); s0.y = fmaf(g0.y, v0.y, s0.y);
        s0.z = fmaf(g0.y, v0.z, s0.z); s0.w = fmaf(g0.y, v0.w, s0.w);
        s1.x = fmaf(g1.y, v1.x, s1.x); s1.y = fmaf(g1.y, v1.y, s1.y);
        s1.z = fmaf(g1.y, v1.z, s1.z); s1.w = fmaf(g1.y, v1.w, s1.w);
        s2.x = fmaf(g2.y, v2.x, s2.x); s2.y = fmaf(g2.y, v2.y, s2.y);
        s2.z = fmaf(g2.y, v2.z, s2.z); s2.w = fmaf(g2.y, v2.w, s2.w);
        s3.x = fmaf(g3.y, v3.x, s3.x); s3.y = fmaf(g3.y, v3.y, s3.y);
        s3.z = fmaf(g3.y, v3.z, s3.z); s3.w = fmaf(g3.y, v3.w, s3.w);
    }
    const float4 x0 = __ldg(f4 + xrow0 + 0*CH4 + tid);
    const float4 x1 = __ldg(f4 + xrow0 + 1*CH4 + tid);
    const float4 x2 = __ldg(f4 + xrow0 + 2*CH4 + tid);
    const float4 x3 = __ldg(f4 + xrow0 + 3*CH4 + tid);

    // (sum w*row)/W - x   (weights normalized in reference)
    s0.x = s0.x*iw0 - x0.x; s0.y = s0.y*iw0 - x0.y; s0.z = s0.z*iw0 - x0.z; s0.w = s0.w*iw0 - x0.w;
    s1.x = s1.x*iw1 - x1.x; s1.y = s1.y*iw1 - x1.y; s1.z = s1.z*iw1 - x1.z; s1.w = s1.w*iw1 - x1.w;
    s2.x = s2.x*iw2 - x2.x; s2.y = s2.y*iw2 - x2.y; s2.z = s2.z*iw2 - x2.z; s2.w = s2.w*iw2 - x2.w;
    s3.x = s3.x*iw3 - x3.x; s3.y = s3.y*iw3 - x3.y; s3.z = s3.z*iw3 - x3.z; s3.w = s3.w*iw3 - x3.w;

    float l0 = s0.x*s0.x + s0.y*s0.y + s0.z*s0.z + s0.w*s0.w;
    float l1 = s1.x*s1.x + s1.y*s1.y + s1.z*s1.z + s1.w*s1.w;
    float l2 = s2.x*s2.x + s2.y*s2.y + s2.z*s2.z + s2.w*s2.w;
    float l3 = s3.x*s3.x + s3.y*s3.y + s3.z*s3.z + s3.w*s3.w;

#pragma unroll
    for (int off = 16; off > 0; off >>= 1) {
        l0 += __shfl_down_sync(0xffffffffu, l0, off);
        l1 += __shfl_down_sync(0xffffffffu, l1, off);
        l2 += __shfl_down_sync(0xffffffffu, l2, off);
        l3 += __shfl_down_sync(0xffffffffu, l3, off);
    }
    if (lane == 0) {
        red[0][w] = l0; red[1][w] = l1; red[2][w] = l2; red[3][w] = l3;
    }
    __syncthreads();
    const float ri0 = rsqrtf((red[0][0]+red[0][1]+red[0][2]) * (1.0f/CH) + RMSEPS);
    const float ri1 = rsqrtf((red[1][0]+red[1][1]+red[1][2]) * (1.0f/CH) + RMSEPS);
    const float ri2 = rsqrtf((red[2][0]+red[2][1]+red[2][2]) * (1.0f/CH) + RMSEPS);
    const float ri3 = rsqrtf((red[3][0]+red[3][1]+red[3][2]) * (1.0f/CH) + RMSEPS);

    const float4 kv  = __ldg((const float4*)knorm_w + tid);
    const float4 r0v = __ldg((const float4*)rf + (1 + n0 + 0) * CH4 + tid);
    const float4 r1v = __ldg((const float4*)rf + (1 + n0 + 1) * CH4 + tid);
    const float4 r2v = __ldg((const float4*)rf + (1 + n0 + 2) * CH4 + tid);
    const float4 r3v = __ldg((const float4*)rf + (1 + n0 + 3) * CH4 + tid);

    float4 o;
    o.x = r0v.x + x0.x + s0.x*ri0*kv.x; o.y = r0v.y + x0.y + s0.y*ri0*kv.y;
    o.z = r0v.z + x0.z + s0.z*ri0*kv.z; o.w = r0v.w + x0.w + s0.w*ri0*kv.w;
    ((float4*)out)[xrow0 + 0*CH4 + tid] = o;
    o.x = r1v.x + x1.x + s1.x*ri1*kv.x; o.y = r1v.y + x1.y + s1.y*ri1*kv.y;
    o.z = r1v.z + x1.z + s1.z*ri1*kv.z; o.w = r1v.w + x1.w + s1.w*ri1*kv.w;
    ((float4*)out)[xrow0 + 1*CH4 + tid] = o;
    o.x = r2v.x + x2.x + s2.x*ri2*kv.x; o.y = r2v.y + x2.y + s2.y*ri2*kv.y;
    o.z = r2v.z + x2.z + s2.z*ri2*kv.z; o.w = r2v.w + x2.w + s2.w*ri2*kv.w;
    ((float4*)out)[xrow0 + 2*CH4 + tid] = o;
    o.x = r3v.x + x3.x + s3.x*ri3*kv.x; o.y = r3v.y + x3.y + s3.y*ri3*kv.y;
    o.z = r3v.z + x3.z + s3.z*ri3*kv.z; o.w = r3v.w + x3.w + s3.w*ri3*kv.w;
    ((float4*)out)[xrow0 + 3*CH4 + tid] = o;
}

extern "C" void kernel_launch(void* const* d_in, const int* in_sizes, int n_in,
                              void* d_out, int out_size)
{
    const float* f        = (const float*)d_in[0];
    const float* distance = (const float*)d_in[1];
    const float* rf       = (const float*)d_in[2];
    const float* knorm_w  = (const float*)d_in[3];
    const int*   idx      = (const int*)d_in[4];
    float*       out      = (float*)d_out;

    K_Rectify_38216619000515_kernel<<<(BSZ * NPT) / 4, 96>>>(
        f, distance, rf, knorm_w, idx, out);
}

// round 8
// speedup vs baseline: 1.0703x; 1.0703x over previous
#include <cuda_runtime.h>

// Problem constants (static per reference)
#define BSZ   128
#define NTOT  129
#define NPT   128          // N
#define GS    16
#define CH    384          // channels
#define CH2   192          // CH / 2  (float2 units per row)
#define CH4   96           // CH / 4
#define EPSW  0.05f
#define RMSEPS 1e-6f

__global__ __launch_bounds__(96, 12)
void K_Rectify_38216619000515_kernel(
    const float* __restrict__ f,        // (B, NTOT, CH)
    const float* __restrict__ distance, // (B, N, GS)
    const float* __restrict__ rf,       // (NTOT, CH)
    const float* __restrict__ knorm_w,  // (CH,)
    const int*   __restrict__ idx,      // (B, N, GS), int32, values in [0, B*N)
    float*       __restrict__ out)      // (B, NTOT, CH)
{
    const int bid = blockIdx.x;          // 0..8191, two points per block
    const int bn0 = bid << 1;
    const int bn1 = bn0 | 1;
    const int tid = threadIdx.x;         // 0..95
    const int w   = tid >> 5;
    const int lane = tid & 31;

    __shared__ float4 sgw[GS];           // (offA bits, wtA, offB bits, wtB), offsets in float2 units
    __shared__ float  red[2][3];

    if (tid < 2 * GS) {
        const int p  = tid >> 4;         // point 0/1
        const int g  = tid & 15;
        const int bn = bn0 + p;
        float d  = distance[bn * GS + g];
        float wt = 1.0f / (d + EPSW);
        int r    = idx[bn * GS + g] & (BSZ * NPT - 1);
        int off2 = ((r >> 7) * NTOT + (r & 127) + 1) * CH2;   // float2 units
        if (p == 0) { sgw[g].x = __int_as_float(off2); sgw[g].y = wt; }
        else        { sgw[g].z = __int_as_float(off2); sgw[g].w = wt; }
    }

    const int b0 = bn0 >> 7, n0 = bn0 & 127;
    const int b1 = bn1 >> 7, n1 = bn1 & 127;   // n1 odd -> never 0

    // cls token passthrough (only point A can have n==0); 96 lanes == CH4
    if (n0 == 0) {
        ((float4*)out)[b0 * (NTOT * CH4) + tid] =
            __ldg((const float4*)f + b0 * (NTOT * CH4) + tid);
    }
    __syncthreads();

    float wsA = 0.0f, wsB = 0.0f;
#pragma unroll
    for (int g = 0; g < GS; ++g) { wsA += sgw[g].y; wsB += sgw[g].w; }
    const float iwA = 1.0f / wsA;
    const float iwB = 1.0f / wsB;

    const float2* f2 = (const float2*)f;
    const int xrowA = (b0 * NTOT + 1 + n0) * CH2;
    const int xrowB = (b1 * NTOT + 1 + n1) * CH2;

    // per-thread channels: float2 slots tid and tid+96 of each 192-float2 row
    float2 aA0 = make_float2(0.f,0.f), aA1 = make_float2(0.f,0.f);
    float2 aB0 = make_float2(0.f,0.f), aB1 = make_float2(0.f,0.f);
#pragma unroll
    for (int g = 0; g < GS; ++g) {
        const float4 q = sgw[g];                 // one LDS.128 broadcast per g
        const int offA = __float_as_int(q.x);
        const int offB = __float_as_int(q.z);
        const float2 vA0 = __ldg(f2 + offA + tid);
        const float2 vA1 = __ldg(f2 + offA + CH4 + tid);
        const float2 vB0 = __ldg(f2 + offB + tid);
        const float2 vB1 = __ldg(f2 + offB + CH4 + tid);
        const float wA = q.y, wB = q.w;
        aA0.x = fmaf(wA, vA0.x, aA0.x); aA0.y = fmaf(wA, vA0.y, aA0.y);
        aA1.x = fmaf(wA, vA1.x, aA1.x); aA1.y = fmaf(wA, vA1.y, aA1.y);
        aB0.x = fmaf(wB, vB0.x, aB0.x); aB0.y = fmaf(wB, vB0.y, aB0.y);
        aB1.x = fmaf(wB, vB1.x, aB1.x); aB1.y = fmaf(wB, vB1.y, aB1.y);
    }
    const float2 xA0 = __ldg(f2 + xrowA + tid);
    const float2 xA1 = __ldg(f2 + xrowA + CH4 + tid);
    const float2 xB0 = __ldg(f2 + xrowB + tid);
    const float2 xB1 = __ldg(f2 + xrowB + CH4 + tid);

    // (sum w*row)/W - x   (weights normalized in reference)
    aA0.x = aA0.x*iwA - xA0.x; aA0.y = aA0.y*iwA - xA0.y;
    aA1.x = aA1.x*iwA - xA1.x; aA1.y = aA1.y*iwA - xA1.y;
    aB0.x = aB0.x*iwB - xB0.x; aB0.y = aB0.y*iwB - xB0.y;
    aB1.x = aB1.x*iwB - xB1.x; aB1.y = aB1.y*iwB - xB1.y;

    float lA = aA0.x*aA0.x + aA0.y*aA0.y + aA1.x*aA1.x + aA1.y*aA1.y;
    float lB = aB0.x*aB0.x + aB0.y*aB0.y + aB1.x*aB1.x + aB1.y*aB1.y;

#pragma unroll
    for (int off = 16; off > 0; off >>= 1) {
        lA += __shfl_down_sync(0xffffffffu, lA, off);
        lB += __shfl_down_sync(0xffffffffu, lB, off);
    }
    if (lane == 0) { red[0][w] = lA; red[1][w] = lB; }
    __syncthreads();
    const float riA = rsqrtf((red[0][0] + red[0][1] + red[0][2]) * (1.0f / CH) + RMSEPS);
    const float riB = rsqrtf((red[1][0] + red[1][1] + red[1][2]) * (1.0f / CH) + RMSEPS);

    const float2* rf2 = (const float2*)rf;
    const float2* kw2 = (const float2*)knorm_w;
    const float2 kv0 = __ldg(kw2 + tid);
    const float2 kv1 = __ldg(kw2 + CH4 + tid);
    const float2 rA0 = __ldg(rf2 + (1 + n0) * CH2 + tid);
    const float2 rA1 = __ldg(rf2 + (1 + n0) * CH2 + CH4 + tid);
    const float2 rB0 = __ldg(rf2 + (1 + n1) * CH2 + tid);
    const float2 rB1 = __ldg(rf2 + (1 + n1) * CH2 + CH4 + tid);

    float2* out2 = (float2*)out;
    float2 o;
    o.x = rA0.x + xA0.x + aA0.x*riA*kv0.x;  o.y = rA0.y + xA0.y + aA0.y*riA*kv0.y;
    out2[xrowA + tid] = o;
    o.x = rA1.x + xA1.x + aA1.x*riA*kv1.x;  o.y = rA1.y + xA1.y + aA1.y*riA*kv1.y;
    out2[xrowA + CH4 + tid] = o;
    o.x = rB0.x + xB0.x + aB0.x*riB*kv0.x;  o.y = rB0.y + xB0.y + aB0.y*riB*kv0.y;
    out2[xrowB + tid] = o;
    o.x = rB1.x + xB1.x + aB1.x*riB*kv1.x;  o.y = rB1.y + xB1.y + aB1.y*riB*kv1.y;
    out2[xrowB + CH4 + tid] = o;
}

extern "C" void kernel_launch(void* const* d_in, const int* in_sizes, int n_in,
                              void* d_out, int out_size)
{
    const float* f        = (const float*)d_in[0];
    const float* distance = (const float*)d_in[1];
    const float* rf       = (const float*)d_in[2];
    const float* knorm_w  = (const float*)d_in[3];
    const int*   idx      = (const int*)d_in[4];
    float*       out      = (float*)d_out;

    K_Rectify_38216619000515_kernel<<<(BSZ * NPT) / 2, 96>>>(
        f, distance, rf, knorm_w, idx, out);
}